// round 1
// baseline (speedup 1.0000x reference)
#include <cuda_runtime.h>
#include <cuda_bf16.h>

// Resample2d: bilinear warp.
// input1: [B=8, D=64, H=384, W=512] fp32
// input2: [B=8, 2,    H=384, W=512] fp32 (u = [:,0], v = [:,1])
// out   : [B=8, D=64, H=384, W=512] fp32
//
// One thread per (b, h, w). Each thread computes flow, clamps, derives the
// 4 bilinear weights + base offsets ONCE, then loops over all 64 channels
// (channel stride = H*W), doing 4 gather loads + 3 FMAs + 1 coalesced store
// per channel. Boundary handling folds x1/y1 into x0/y0 by clamping
// x0 <= W-2 and letting wx -> 1 (identical result to the reference's
// min(x0+1, W-1) formulation).

#define B_ 8
#define D_ 64
#define H_ 384
#define W_ 512

__global__ __launch_bounds__(512, 2)
void resample2d_kernel(const float* __restrict__ img,
                       const float* __restrict__ flow,
                       float* __restrict__ out)
{
    const int w  = threadIdx.x;          // 0..511
    const int bh = blockIdx.x;           // 0..B*H-1
    const int b  = bh / H_;
    const int h  = bh - b * H_;

    // flow layout [B, 2, H, W]
    const long foff = (long)b * 2 * H_ * W_ + (long)h * W_ + w;
    const float u = __ldg(flow + foff);
    const float v = __ldg(flow + foff + (long)H_ * W_);

    float fx = (float)w + u;
    float fy = (float)h + v;
    fx = fminf(fmaxf(fx, 0.0f), (float)(W_ - 1));
    fy = fminf(fmaxf(fy, 0.0f), (float)(H_ - 1));

    // floor (fx,fy >= 0 so trunc == floor), clamp so x1=x0+1 / y1=y0+1 stay in range
    int x0 = min((int)fx, W_ - 2);
    int y0 = min((int)fy, H_ - 2);
    const float wx = fx - (float)x0;
    const float wy = fy - (float)y0;

    const float w00 = (1.0f - wy) * (1.0f - wx);
    const float w01 = (1.0f - wy) * wx;
    const float w10 = wy * (1.0f - wx);
    const float w11 = wy * wx;

    const long plane = (long)H_ * W_;                       // per-channel stride
    const float* p00 = img + (long)b * D_ * plane + (long)y0 * W_ + x0; // (y0,x0), d=0
    const float* p10 = p00 + W_;                                        // (y1,x0), d=0
    float*       po  = out + (long)b * D_ * plane + (long)h * W_ + w;

    #pragma unroll 8
    for (int d = 0; d < D_; ++d) {
        const float* q0 = p00 + (long)d * plane;
        const float* q1 = p10 + (long)d * plane;
        float a00 = __ldg(q0);
        float a01 = __ldg(q0 + 1);
        float a10 = __ldg(q1);
        float a11 = __ldg(q1 + 1);
        float r = w00 * a00;
        r = fmaf(w01, a01, r);
        r = fmaf(w10, a10, r);
        r = fmaf(w11, a11, r);
        po[(long)d * plane] = r;
    }
}

extern "C" void kernel_launch(void* const* d_in, const int* in_sizes, int n_in,
                              void* d_out, int out_size)
{
    const float* img  = (const float*)d_in[0];
    const float* flow = (const float*)d_in[1];
    float* out = (float*)d_out;

    dim3 grid(B_ * H_);
    dim3 block(W_);
    resample2d_kernel<<<grid, block>>>(img, flow, out);
}

// round 2
// speedup vs baseline: 1.0084x; 1.0084x over previous
#include <cuda_runtime.h>
#include <cuda_bf16.h>

// Resample2d: bilinear warp.
// input1: [B=8, D=64, H=384, W=512] fp32
// input2: [B=8, 2,    H=384, W=512] fp32 (u = [:,0], v = [:,1])
// out   : [B=8, D=64, H=384, W=512] fp32
//
// One thread per (b, h, w): compute flow/weights/base offsets once, loop over
// 64 channels with stride H*W. All offsets kept as 32-bit unsigned element
// indices (tensor is 100.6M elements < 2^31) to cut register pressure and
// raise occupancy — round-1 profile showed L1tex 83.8% / occ 47.3% / issue
// 13.9%, i.e. gather latency not hidden.

#define B_ 8
#define D_ 64
#define H_ 384
#define W_ 512
#define PLANE_ (H_ * W_)          // 196608
#define TPB 256

__global__ __launch_bounds__(TPB)
void resample2d_kernel(const float* __restrict__ img,
                       const float* __restrict__ flow,
                       float* __restrict__ out)
{
    // grid: B*H*(W/TPB) blocks; blockIdx.x = (b*H + h)*(W/TPB) + wchunk
    const int WCHUNKS = W_ / TPB;                 // 2
    int bid = blockIdx.x;
    const int wchunk = bid % WCHUNKS;
    bid /= WCHUNKS;
    const int h = bid % H_;
    const int b = bid / H_;
    const int w = wchunk * TPB + threadIdx.x;

    // flow layout [B, 2, H, W]
    const unsigned foff = (unsigned)b * (2u * PLANE_) + (unsigned)h * W_ + w;
    const float u = __ldg(flow + foff);
    const float v = __ldg(flow + foff + PLANE_);

    float fx = (float)w + u;
    float fy = (float)h + v;
    fx = fminf(fmaxf(fx, 0.0f), (float)(W_ - 1));
    fy = fminf(fmaxf(fy, 0.0f), (float)(H_ - 1));

    // fx,fy >= 0 so trunc == floor; clamp so x0+1 / y0+1 stay in range.
    const int x0 = min((int)fx, W_ - 2);
    const int y0 = min((int)fy, H_ - 2);
    const float wx = fx - (float)x0;
    const float wy = fy - (float)y0;

    const float w00 = (1.0f - wy) * (1.0f - wx);
    const float w01 = (1.0f - wy) * wx;
    const float w10 = wy * (1.0f - wx);
    const float w11 = wy * wx;

    // 32-bit element offsets (max: 8*64*196608 = 100,663,296 < 2^31)
    unsigned o0 = (unsigned)b * (D_ * PLANE_) + (unsigned)y0 * W_ + (unsigned)x0;
    unsigned o1 = o0 + W_;
    unsigned oo = (unsigned)b * (D_ * PLANE_) + (unsigned)h * W_ + (unsigned)w;

    #pragma unroll 8
    for (int d = 0; d < D_; ++d) {
        const float a00 = __ldg(img + o0);
        const float a01 = __ldg(img + o0 + 1);
        const float a10 = __ldg(img + o1);
        const float a11 = __ldg(img + o1 + 1);
        float r = w00 * a00;
        r = fmaf(w01, a01, r);
        r = fmaf(w10, a10, r);
        r = fmaf(w11, a11, r);
        out[oo] = r;
        o0 += PLANE_;
        o1 += PLANE_;
        oo += PLANE_;
    }
}

extern "C" void kernel_launch(void* const* d_in, const int* in_sizes, int n_in,
                              void* d_out, int out_size)
{
    const float* img  = (const float*)d_in[0];
    const float* flow = (const float*)d_in[1];
    float* out = (float*)d_out;

    dim3 grid(B_ * H_ * (W_ / TPB));
    dim3 block(TPB);
    resample2d_kernel<<<grid, block>>>(img, flow, out);
}